// round 15
// baseline (speedup 1.0000x reference)
#include <cuda_runtime.h>
#include <cuda_bf16.h>

#define BB 32
#define CC 64
#define TT 2048
#define KK 16
#define NST 6

#define TILE 32                          // t-range per CTA (grid 4096, ~93% wave fill)
#define HALO_L 16                        // 15 causal + 1 for float4 alignment
#define ROWS 50                          // scalar fill (16 + 32 + 2)
#define ROWV 56                          // vector fill (14 float4)
#define PITCH 60                         // mult-4; 60%32=28 -> distinct banks per channel
#define CH 32                            // channels per CTA
#define NTH 128                          // 32 channels x 4 K-quarters
#define NTILES (TT / TILE)               // 64
#define LOG2E 1.4426950408889634f

typedef unsigned long long ull;

__device__ float g_means[BB * CC];

__device__ __forceinline__ float sqrt_approx(float x) {
    float r; asm("sqrt.approx.f32 %0, %1;" : "=f"(r) : "f"(x)); return r;
}
__device__ __forceinline__ float rcp_approx(float x) {
    float r; asm("rcp.approx.f32 %0, %1;" : "=f"(r) : "f"(x)); return r;
}
__device__ __forceinline__ float ex2_approx(float x) {
    float r; asm("ex2.approx.f32 %0, %1;" : "=f"(r) : "f"(x)); return r;
}
__device__ __forceinline__ float apply_sign(float ev, float k) {
    return __uint_as_float(__float_as_uint(ev) | (__float_as_uint(k) & 0x80000000u));
}
// packed f32x2 helpers (Blackwell)
__device__ __forceinline__ ull pack2(float lo, float hi) {
    ull r; asm("mov.b64 %0, {%1, %2};" : "=l"(r) : "f"(lo), "f"(hi)); return r;
}
__device__ __forceinline__ ull pack2dup(float v) {
    ull r; asm("mov.b64 %0, {%1, %1};" : "=l"(r) : "f"(v)); return r;
}
__device__ __forceinline__ float2 unpack2(ull v) {
    float2 r; asm("mov.b64 {%0, %1}, %2;" : "=f"(r.x), "=f"(r.y) : "l"(v)); return r;
}
__device__ __forceinline__ ull fma2(ull a, ull b, ull c) {
    ull r; asm("fma.rn.f32x2 %0, %1, %2, %3;" : "=l"(r) : "l"(a), "l"(b), "l"(c));
    return r;
}

// ---------------------------------------------------------------------------
// Kernel 1: per-(b,c) mean over T (float4 loads)
// ---------------------------------------------------------------------------
__global__ void mean_kernel(const float* __restrict__ x) {
    int row = blockIdx.x;
    const float4* xr = reinterpret_cast<const float4*>(x + (size_t)row * TT);
    float s = 0.f;
    for (int t = threadIdx.x; t < TT / 4; t += blockDim.x) {
        float4 v = xr[t];
        s += (v.x + v.y) + (v.z + v.w);
    }
    __shared__ float red[8];
    #pragma unroll
    for (int o = 16; o > 0; o >>= 1) s += __shfl_down_sync(0xffffffffu, s, o);
    if ((threadIdx.x & 31) == 0) red[threadIdx.x >> 5] = s;
    __syncthreads();
    if (threadIdx.x < 8) {
        s = red[threadIdx.x];
        #pragma unroll
        for (int o = 4; o > 0; o >>= 1) s += __shfl_down_sync(0xffu, s, o);
        if (threadIdx.x == 0) g_means[row] = s * (1.0f / TT);
    }
}

// ---------------------------------------------------------------------------
// Strip of 4 items. Lane q: stats for item m=q (4 shfl broadcasts; xv via
// aligned LDS.128), conv for K-quarter [4q,4q+4) via packed FFMA2 k-pairs,
// SEL-steered reduce-scatter -> lane q stores item q.
// vlo is the rolling low half of the gather window (carried across strips).
// ---------------------------------------------------------------------------
template <bool EDGE>
__device__ __forceinline__ void do_strip(
    const float* __restrict__ xc,   // xc[i] == x[b,c,t0+i] (smem, zero-pad)
    int tl, int q,
    float4& vlo,                    // rolling: covers xc[tl+k0-16 .. tl+k0-13]
    const ull* __restrict__ wp,     // 10 x u64: per k-pair {w_j k0, w_j k1}*LOG2E
    const ull* __restrict__ bsp,    // 2 x u64 packed bias
    float* __restrict__ outq,       // &out[b, t0+q, c]
    int tg0)
{
    const int k0 = q * 4;

    // gather taps: vg[i] = x[t0 + tl + k0 - 16 + i]; lo rolled, hi loaded
    const float4 vhi = *reinterpret_cast<const float4*>(xc + tl + k0 - 12);
    float vg[8];
    vg[0] = vlo.x; vg[1] = vlo.y; vg[2] = vlo.z; vg[3] = vlo.w;
    vg[4] = vhi.x; vg[5] = vhi.y; vg[6] = vhi.z; vg[7] = vhi.w;
    vlo = vhi;                      // next strip's lo

    // center values of the 4 items (one aligned LDS.128)
    const float4 xq = *reinterpret_cast<const float4*>(xc + tl);

    // ---- own-item stats (item m = q, t = t0 + tl + q) ----
    const int ts = tl + q;
    const float a0 = xc[ts - 2], a1 = xc[ts - 1], a2 = xc[ts],
                a3 = xc[ts + 1], a4 = xc[ts + 2];
    const float s  = ((a0 + a1) + (a2 + a3)) + a4;
    const float s2 = fmaf(a0, a0, a1 * a1)
                   + fmaf(a2, a2, fmaf(a3, a3, a4 * a4));
    const float avg = s * 0.2f;
    const float sd  = sqrt_approx(fmaxf(fmaf(-avg, avg, s2 * 0.2f), 1e-6f));
    const float dd  = a2 - avg;
    const float tm  = dd * dd * dd;

    float mx, mn;
    if (EDGE) {
        mx = -3.402823466e38f; mn = 3.402823466e38f;
        const int tg = tg0 + q;
        #pragma unroll
        for (int j = -2; j <= 2; j++) {
            int g = tg + j;
            if (g >= 0 && g < TT) {
                float t = xc[ts + j];
                mx = fmaxf(mx, t); mn = fminf(mn, t);
            }
        }
    } else {
        mx = fmaxf(fmaxf(fmaxf(a0, a1), fmaxf(a2, a3)), a4);
        mn = fminf(fminf(fminf(a0, a1), fminf(a2, a3)), a4);
    }

    // ---- 4 items: broadcast stats, packed conv + exp + partial sums ----
    float sp[4], ap[4];
    #pragma unroll
    for (int m = 0; m < 4; m++) {
        const float xv_m = (m == 0) ? xq.x : (m == 1) ? xq.y
                         : (m == 2) ? xq.z : xq.w;
        const float sd_m = __shfl_sync(0xffffffffu, sd, m, 4);
        const float tm_m = __shfl_sync(0xffffffffu, tm, m, 4);
        const float mx_m = __shfl_sync(0xffffffffu, mx, m, 4);
        const float mn_m = __shfl_sync(0xffffffffu, mn, m, 4);

        const ull xv2 = pack2dup(xv_m);
        const ull sd2 = pack2dup(sd_m);
        const ull tm2 = pack2dup(tm_m);
        const ull mx2 = pack2dup(mx_m);
        const ull mn2 = pack2dup(mn_m);

        float kern[4], ev[4];
        #pragma unroll
        for (int p = 0; p < 2; p++) {
            ull a = bsp[p];
            a = fma2(wp[p * 5 + 0], xv2, a);
            a = fma2(wp[p * 5 + 1], sd2, a);
            a = fma2(wp[p * 5 + 2], tm2, a);
            a = fma2(wp[p * 5 + 3], mx2, a);
            a = fma2(wp[p * 5 + 4], mn2, a);
            float2 kk = unpack2(a);
            kern[2 * p]     = kk.x;
            kern[2 * p + 1] = kk.y;
        }
        #pragma unroll
        for (int k = 0; k < 4; k++) ev[k] = ex2_approx(fabsf(kern[k]));
        #pragma unroll
        for (int k = 0; k < 4; k++)
            kern[k] = vg[1 + m + k] * apply_sign(ev[k], kern[k]);

        sp[m] = (ev[0] + ev[1]) + (ev[2] + ev[3]);
        ap[m] = (kern[0] + kern[1]) + (kern[2] + kern[3]);
    }

    // ---- reduce-scatter over the 4-lane group: lane q ends with item q ----
    const bool hi2 = (q & 2) != 0;
    const bool hi1 = (q & 1) != 0;

    float sk0 = hi2 ? sp[2] : sp[0];
    float sk1 = hi2 ? sp[3] : sp[1];
    float ss0 = hi2 ? sp[0] : sp[2];
    float ss1 = hi2 ? sp[1] : sp[3];
    float ak0 = hi2 ? ap[2] : ap[0];
    float ak1 = hi2 ? ap[3] : ap[1];
    float as0 = hi2 ? ap[0] : ap[2];
    float as1 = hi2 ? ap[1] : ap[3];
    sk0 += __shfl_xor_sync(0xffffffffu, ss0, 2);
    sk1 += __shfl_xor_sync(0xffffffffu, ss1, 2);
    ak0 += __shfl_xor_sync(0xffffffffu, as0, 2);
    ak1 += __shfl_xor_sync(0xffffffffu, as1, 2);

    float skeep = hi1 ? sk1 : sk0;
    float ssend = hi1 ? sk0 : sk1;
    float akeep = hi1 ? ak1 : ak0;
    float asend = hi1 ? ak0 : ak1;
    float S = skeep + __shfl_xor_sync(0xffffffffu, ssend, 1);
    float A = akeep + __shfl_xor_sync(0xffffffffu, asend, 1);

    outq[tl * CC] = A * rcp_approx(S);
}

// ---------------------------------------------------------------------------
// Kernel 2: CTA = 128 threads = 32 channels x 4 K-quarters, 32 t's per CTA.
// 8 CTAs/SM, grid 4096 (3.46 waves, ~93% fill).
// ---------------------------------------------------------------------------
extern __shared__ float smem[];

__global__ __launch_bounds__(NTH, 8)
void ddst_main_kernel(const float* __restrict__ x,
                      const float* __restrict__ W,
                      const float* __restrict__ bias,
                      float* __restrict__ out) {
    float* xs = smem;                   // [CH][PITCH]

    const int bt   = blockIdx.x >> 1;          // b * NTILES + tile
    const int ch0  = (blockIdx.x & 1) * CH;    // channel group base
    const int b    = bt / NTILES;
    const int tile = bt % NTILES;
    const int t0   = tile * TILE;
    const int tid  = threadIdx.x;

    const float* xb = x + ((size_t)b * CC + ch0) * TT;
    const bool edge = (tile == 0) || (tile == NTILES - 1);

    // x tile + halo
    if (!edge) {
        const int NV = ROWV / 4;               // 14 float4 per row
        for (int idx = tid; idx < CH * NV; idx += NTH) {
            int cr = idx / NV;
            int j  = idx - cr * NV;
            const float4* src4 =
                reinterpret_cast<const float4*>(xb + (size_t)cr * TT + t0 - HALO_L);
            reinterpret_cast<float4*>(xs + cr * PITCH)[j] = src4[j];
        }
    } else {
        const int warp = tid >> 5;
        const int lane = tid & 31;
        for (int cr = warp; cr < CH; cr += NTH / 32) {
            const float* src = xb + (size_t)cr * TT;
            float* dst = xs + cr * PITCH;
            for (int j = lane; j < ROWS; j += 32) {
                int gt = t0 - HALO_L + j;
                dst[j] = (gt >= 0 && gt < TT) ? src[gt] : 0.f;
            }
        }
    }
    __syncthreads();

    const int cl = tid >> 2;          // 0..31 local channel
    const int q  = tid & 3;           // quarter = stats-item = store-item
    const int k0 = q * 4;
    const int c  = ch0 + cl;

    // per-thread weights: packed k-pairs {w_j[2p], w_j[2p+1]} * LOG2E
    const float gm = g_means[b * CC + c];
    const float* Wp = W + c * (KK * NST) + k0 * NST;
    ull wp[10], bsp[2];
    #pragma unroll
    for (int p = 0; p < 2; p++) {
        const float* wa = Wp + (2 * p) * NST;
        const float* wb = Wp + (2 * p + 1) * NST;
        wp[p * 5 + 0] = pack2(__ldg(wa + 0) * LOG2E, __ldg(wb + 0) * LOG2E);
        wp[p * 5 + 1] = pack2(__ldg(wa + 2) * LOG2E, __ldg(wb + 2) * LOG2E);
        wp[p * 5 + 2] = pack2(__ldg(wa + 3) * LOG2E, __ldg(wb + 3) * LOG2E);
        wp[p * 5 + 3] = pack2(__ldg(wa + 4) * LOG2E, __ldg(wb + 4) * LOG2E);
        wp[p * 5 + 4] = pack2(__ldg(wa + 5) * LOG2E, __ldg(wb + 5) * LOG2E);
        float ba = fmaf(__ldg(wa + 1), gm,
                        __ldg(&bias[c * KK + k0 + 2 * p])) * LOG2E;
        float bb = fmaf(__ldg(wb + 1), gm,
                        __ldg(&bias[c * KK + k0 + 2 * p + 1])) * LOG2E;
        bsp[p] = pack2(ba, bb);
    }

    const float* xc = xs + cl * PITCH + HALO_L;
    float* outq = out + ((size_t)b * TT + t0 + q) * CC + c;

    // rolling low half of the gather window for strip tl=0
    float4 vlo = *reinterpret_cast<const float4*>(xc + k0 - 16);

    if (edge) {
        #pragma unroll 4
        for (int i = 0; i < TILE / 4; i++) {
            int tl = i * 4;
            do_strip<true>(xc, tl, q, vlo, wp, bsp, outq, t0 + tl);
        }
    } else {
        #pragma unroll 4
        for (int i = 0; i < TILE / 4; i++) {
            int tl = i * 4;
            do_strip<false>(xc, tl, q, vlo, wp, bsp, outq, t0 + tl);
        }
    }
}

// ---------------------------------------------------------------------------
extern "C" void kernel_launch(void* const* d_in, const int* in_sizes, int n_in,
                              void* d_out, int out_size) {
    const float* x    = (const float*)d_in[0];   // [B, C, T]
    const float* W    = (const float*)d_in[1];   // [C, K, 6]
    const float* bias = (const float*)d_in[2];   // [C, K]
    float* out = (float*)d_out;                  // [B, T, C]

    (void)in_sizes; (void)n_in; (void)out_size;

    mean_kernel<<<BB * CC, 256>>>(x);

    const int smem_bytes = (CH * PITCH) * (int)sizeof(float);
    cudaFuncSetAttribute(ddst_main_kernel,
                         cudaFuncAttributeMaxDynamicSharedMemorySize, smem_bytes);
    ddst_main_kernel<<<BB * NTILES * 2, NTH, smem_bytes>>>(x, W, bias, out);
}

// round 16
// speedup vs baseline: 1.0905x; 1.0905x over previous
#include <cuda_runtime.h>
#include <cuda_bf16.h>

#define BB 32
#define CC 64
#define TT 2048
#define KK 16
#define NST 6

#define TILE 64                          // t-range per CTA (grid 2048)
#define HALO_L 16                        // 15 causal + 1 for float4 alignment
#define ROWS 82                          // scalar fill (16 + 64 + 2)
#define ROWV 88                          // vector fill (22 float4)
#define PITCH 92                         // mult-4; conflict-free across channels
#define CH 32                            // channels per CTA
#define NTH 128                          // 32 channels x 4 K-quarters
#define NTILES (TT / TILE)               // 32
#define LOG2E 1.4426950408889634f

typedef unsigned long long ull;

__device__ float g_means[BB * CC];

__device__ __forceinline__ float sqrt_approx(float x) {
    float r; asm("sqrt.approx.f32 %0, %1;" : "=f"(r) : "f"(x)); return r;
}
__device__ __forceinline__ float rcp_approx(float x) {
    float r; asm("rcp.approx.f32 %0, %1;" : "=f"(r) : "f"(x)); return r;
}
__device__ __forceinline__ float ex2_approx(float x) {
    float r; asm("ex2.approx.f32 %0, %1;" : "=f"(r) : "f"(x)); return r;
}
__device__ __forceinline__ float apply_sign(float ev, float k) {
    return __uint_as_float(__float_as_uint(ev) | (__float_as_uint(k) & 0x80000000u));
}
// packed f32x2 helpers (Blackwell)
__device__ __forceinline__ ull pack2(float lo, float hi) {
    ull r; asm("mov.b64 %0, {%1, %2};" : "=l"(r) : "f"(lo), "f"(hi)); return r;
}
__device__ __forceinline__ ull pack2dup(float v) {
    ull r; asm("mov.b64 %0, {%1, %1};" : "=l"(r) : "f"(v)); return r;
}
__device__ __forceinline__ float2 unpack2(ull v) {
    float2 r; asm("mov.b64 {%0, %1}, %2;" : "=f"(r.x), "=f"(r.y) : "l"(v)); return r;
}
__device__ __forceinline__ ull fma2(ull a, ull b, ull c) {
    ull r; asm("fma.rn.f32x2 %0, %1, %2, %3;" : "=l"(r) : "l"(a), "l"(b), "l"(c));
    return r;
}

// ---------------------------------------------------------------------------
// Kernel 1: per-(b,c) mean over T (float4 loads)
// ---------------------------------------------------------------------------
__global__ void mean_kernel(const float* __restrict__ x) {
    int row = blockIdx.x;
    const float4* xr = reinterpret_cast<const float4*>(x + (size_t)row * TT);
    float s = 0.f;
    for (int t = threadIdx.x; t < TT / 4; t += blockDim.x) {
        float4 v = xr[t];
        s += (v.x + v.y) + (v.z + v.w);
    }
    __shared__ float red[8];
    #pragma unroll
    for (int o = 16; o > 0; o >>= 1) s += __shfl_down_sync(0xffffffffu, s, o);
    if ((threadIdx.x & 31) == 0) red[threadIdx.x >> 5] = s;
    __syncthreads();
    if (threadIdx.x < 8) {
        s = red[threadIdx.x];
        #pragma unroll
        for (int o = 4; o > 0; o >>= 1) s += __shfl_down_sync(0xffu, s, o);
        if (threadIdx.x == 0) g_means[row] = s * (1.0f / TT);
    }
}

// ---------------------------------------------------------------------------
// Strip of 4 items. Lane q: stats for item m=q (4 shfl broadcasts; xv via
// aligned LDS.128), conv for K-quarter [4q,4q+4) via packed FFMA2 k-pairs,
// SEL-steered reduce-scatter -> lane q stores item q.
// ---------------------------------------------------------------------------
template <bool EDGE>
__device__ __forceinline__ void do_strip(
    const float* __restrict__ xc,   // xc[i] == x[b,c,t0+i] (smem, zero-pad)
    int tl, int q,
    const ull* __restrict__ wp,     // 10 x u64: per k-pair {w_j k0, w_j k1}*LOG2E
    const ull* __restrict__ bsp,    // 2 x u64 packed bias
    float* __restrict__ outq,       // &out[b, t0+q, c]
    int tg0)
{
    const int k0 = q * 4;

    // gather taps: vg[i] = x[t0 + tl + k0 - 16 + i]; aligned 2x float4
    float vg[8];
    {
        const float4* p = reinterpret_cast<const float4*>(xc + tl + k0 - 16);
        float4 lo = p[0], hi = p[1];
        vg[0] = lo.x; vg[1] = lo.y; vg[2] = lo.z; vg[3] = lo.w;
        vg[4] = hi.x; vg[5] = hi.y; vg[6] = hi.z; vg[7] = hi.w;
    }
    // center values of the 4 items (one aligned LDS.128)
    const float4 xq = *reinterpret_cast<const float4*>(xc + tl);

    // ---- own-item stats (item m = q, t = t0 + tl + q) ----
    const int ts = tl + q;
    const float a0 = xc[ts - 2], a1 = xc[ts - 1], a2 = xc[ts],
                a3 = xc[ts + 1], a4 = xc[ts + 2];
    const float s  = ((a0 + a1) + (a2 + a3)) + a4;
    const float s2 = fmaf(a0, a0, a1 * a1)
                   + fmaf(a2, a2, fmaf(a3, a3, a4 * a4));
    const float avg = s * 0.2f;
    const float sd  = sqrt_approx(fmaxf(fmaf(-avg, avg, s2 * 0.2f), 1e-6f));
    const float dd  = a2 - avg;
    const float tm  = dd * dd * dd;

    float mx, mn;
    if (EDGE) {
        mx = -3.402823466e38f; mn = 3.402823466e38f;
        const int tg = tg0 + q;
        #pragma unroll
        for (int j = -2; j <= 2; j++) {
            int g = tg + j;
            if (g >= 0 && g < TT) {
                float t = xc[ts + j];
                mx = fmaxf(mx, t); mn = fminf(mn, t);
            }
        }
    } else {
        mx = fmaxf(fmaxf(fmaxf(a0, a1), fmaxf(a2, a3)), a4);
        mn = fminf(fminf(fminf(a0, a1), fminf(a2, a3)), a4);
    }

    // ---- 4 items: broadcast stats, packed conv + exp + partial sums ----
    float sp[4], ap[4];
    #pragma unroll
    for (int m = 0; m < 4; m++) {
        const float xv_m = (m == 0) ? xq.x : (m == 1) ? xq.y
                         : (m == 2) ? xq.z : xq.w;
        const float sd_m = __shfl_sync(0xffffffffu, sd, m, 4);
        const float tm_m = __shfl_sync(0xffffffffu, tm, m, 4);
        const float mx_m = __shfl_sync(0xffffffffu, mx, m, 4);
        const float mn_m = __shfl_sync(0xffffffffu, mn, m, 4);

        const ull xv2 = pack2dup(xv_m);
        const ull sd2 = pack2dup(sd_m);
        const ull tm2 = pack2dup(tm_m);
        const ull mx2 = pack2dup(mx_m);
        const ull mn2 = pack2dup(mn_m);

        float kern[4], ev[4];
        #pragma unroll
        for (int p = 0; p < 2; p++) {
            ull a = bsp[p];
            a = fma2(wp[p * 5 + 0], xv2, a);
            a = fma2(wp[p * 5 + 1], sd2, a);
            a = fma2(wp[p * 5 + 2], tm2, a);
            a = fma2(wp[p * 5 + 3], mx2, a);
            a = fma2(wp[p * 5 + 4], mn2, a);
            float2 kk = unpack2(a);
            kern[2 * p]     = kk.x;
            kern[2 * p + 1] = kk.y;
        }
        #pragma unroll
        for (int k = 0; k < 4; k++) ev[k] = ex2_approx(fabsf(kern[k]));
        #pragma unroll
        for (int k = 0; k < 4; k++)
            kern[k] = vg[1 + m + k] * apply_sign(ev[k], kern[k]);

        sp[m] = (ev[0] + ev[1]) + (ev[2] + ev[3]);
        ap[m] = (kern[0] + kern[1]) + (kern[2] + kern[3]);
    }

    // ---- reduce-scatter over the 4-lane group: lane q ends with item q ----
    const bool hi2 = (q & 2) != 0;
    const bool hi1 = (q & 1) != 0;

    float sk0 = hi2 ? sp[2] : sp[0];
    float sk1 = hi2 ? sp[3] : sp[1];
    float ss0 = hi2 ? sp[0] : sp[2];
    float ss1 = hi2 ? sp[1] : sp[3];
    float ak0 = hi2 ? ap[2] : ap[0];
    float ak1 = hi2 ? ap[3] : ap[1];
    float as0 = hi2 ? ap[0] : ap[2];
    float as1 = hi2 ? ap[1] : ap[3];
    sk0 += __shfl_xor_sync(0xffffffffu, ss0, 2);
    sk1 += __shfl_xor_sync(0xffffffffu, ss1, 2);
    ak0 += __shfl_xor_sync(0xffffffffu, as0, 2);
    ak1 += __shfl_xor_sync(0xffffffffu, as1, 2);

    float skeep = hi1 ? sk1 : sk0;
    float ssend = hi1 ? sk0 : sk1;
    float akeep = hi1 ? ak1 : ak0;
    float asend = hi1 ? ak0 : ak1;
    float S = skeep + __shfl_xor_sync(0xffffffffu, ssend, 1);
    float A = akeep + __shfl_xor_sync(0xffffffffu, asend, 1);

    outq[tl * CC] = A * rcp_approx(S);
}

// ---------------------------------------------------------------------------
// Kernel 2: CTA = 128 threads = 32 channels x 4 K-quarters, 64 t's per CTA.
// 7 CTAs/SM (reg cap 72 -> FFMA2 pair scheduling freedom), grid 2048.
// ---------------------------------------------------------------------------
extern __shared__ float smem[];

__global__ __launch_bounds__(NTH, 7)
void ddst_main_kernel(const float* __restrict__ x,
                      const float* __restrict__ W,
                      const float* __restrict__ bias,
                      float* __restrict__ out) {
    float* xs = smem;                   // [CH][PITCH]

    const int bt   = blockIdx.x >> 1;          // b * NTILES + tile
    const int ch0  = (blockIdx.x & 1) * CH;    // channel group base
    const int b    = bt / NTILES;
    const int tile = bt % NTILES;
    const int t0   = tile * TILE;
    const int tid  = threadIdx.x;

    const float* xb = x + ((size_t)b * CC + ch0) * TT;
    const bool edge = (tile == 0) || (tile == NTILES - 1);

    // x tile + halo
    if (!edge) {
        const int NV = ROWV / 4;               // 22 float4 per row
        for (int idx = tid; idx < CH * NV; idx += NTH) {
            int cr = idx / NV;
            int j  = idx - cr * NV;
            const float4* src4 =
                reinterpret_cast<const float4*>(xb + (size_t)cr * TT + t0 - HALO_L);
            reinterpret_cast<float4*>(xs + cr * PITCH)[j] = src4[j];
        }
    } else {
        const int warp = tid >> 5;
        const int lane = tid & 31;
        for (int cr = warp; cr < CH; cr += NTH / 32) {
            const float* src = xb + (size_t)cr * TT;
            float* dst = xs + cr * PITCH;
            for (int j = lane; j < ROWS; j += 32) {
                int gt = t0 - HALO_L + j;
                dst[j] = (gt >= 0 && gt < TT) ? src[gt] : 0.f;
            }
        }
    }
    __syncthreads();

    const int cl = tid >> 2;          // 0..31 local channel
    const int q  = tid & 3;           // quarter = stats-item = store-item
    const int k0 = q * 4;
    const int c  = ch0 + cl;

    // per-thread weights: packed k-pairs {w_j[2p], w_j[2p+1]} * LOG2E
    const float gm = g_means[b * CC + c];
    const float* Wp = W + c * (KK * NST) + k0 * NST;
    ull wp[10], bsp[2];
    #pragma unroll
    for (int p = 0; p < 2; p++) {
        const float* wa = Wp + (2 * p) * NST;
        const float* wb = Wp + (2 * p + 1) * NST;
        wp[p * 5 + 0] = pack2(__ldg(wa + 0) * LOG2E, __ldg(wb + 0) * LOG2E);
        wp[p * 5 + 1] = pack2(__ldg(wa + 2) * LOG2E, __ldg(wb + 2) * LOG2E);
        wp[p * 5 + 2] = pack2(__ldg(wa + 3) * LOG2E, __ldg(wb + 3) * LOG2E);
        wp[p * 5 + 3] = pack2(__ldg(wa + 4) * LOG2E, __ldg(wb + 4) * LOG2E);
        wp[p * 5 + 4] = pack2(__ldg(wa + 5) * LOG2E, __ldg(wb + 5) * LOG2E);
        float ba = fmaf(__ldg(wa + 1), gm,
                        __ldg(&bias[c * KK + k0 + 2 * p])) * LOG2E;
        float bb = fmaf(__ldg(wb + 1), gm,
                        __ldg(&bias[c * KK + k0 + 2 * p + 1])) * LOG2E;
        bsp[p] = pack2(ba, bb);
    }

    const float* xc = xs + cl * PITCH + HALO_L;
    float* outq = out + ((size_t)b * TT + t0 + q) * CC + c;

    if (edge) {
        #pragma unroll 4
        for (int i = 0; i < TILE / 4; i++) {
            int tl = i * 4;
            do_strip<true>(xc, tl, q, wp, bsp, outq, t0 + tl);
        }
    } else {
        #pragma unroll 4
        for (int i = 0; i < TILE / 4; i++) {
            int tl = i * 4;
            do_strip<false>(xc, tl, q, wp, bsp, outq, t0 + tl);
        }
    }
}

// ---------------------------------------------------------------------------
extern "C" void kernel_launch(void* const* d_in, const int* in_sizes, int n_in,
                              void* d_out, int out_size) {
    const float* x    = (const float*)d_in[0];   // [B, C, T]
    const float* W    = (const float*)d_in[1];   // [C, K, 6]
    const float* bias = (const float*)d_in[2];   // [C, K]
    float* out = (float*)d_out;                  // [B, T, C]

    (void)in_sizes; (void)n_in; (void)out_size;

    mean_kernel<<<BB * CC, 256>>>(x);

    const int smem_bytes = (CH * PITCH) * (int)sizeof(float);
    cudaFuncSetAttribute(ddst_main_kernel,
                         cudaFuncAttributeMaxDynamicSharedMemorySize, smem_bytes);
    ddst_main_kernel<<<BB * NTILES * 2, NTH, smem_bytes>>>(x, W, bias, out);
}